// round 1
// baseline (speedup 1.0000x reference)
#include <cuda_runtime.h>

#define D 2048
#define NROWS 4096     // B*S
#define NHEADS 32
#define HDIM 64
#define SEQ 1024
#define NBATCH 4

// Scratch (allocation-free rule: __device__ globals)
__device__ float g_h [NROWS * D];
__device__ float g_x2[NROWS * D];
__device__ float g_q [NROWS * D];
__device__ float g_k [NROWS * D];
__device__ float g_h2[NROWS * D];
__device__ float g_t [NROWS * D];

// ---------------------------------------------------------------------------
// Block reductions (256 threads)
// ---------------------------------------------------------------------------
__device__ __forceinline__ float blockReduceSum256(float v, float* sh) {
    int tid = threadIdx.x;
    #pragma unroll
    for (int o = 16; o > 0; o >>= 1) v += __shfl_xor_sync(0xffffffffu, v, o);
    if ((tid & 31) == 0) sh[tid >> 5] = v;
    __syncthreads();
    if (tid < 8) {
        float w = sh[tid];
        #pragma unroll
        for (int o = 4; o > 0; o >>= 1) w += __shfl_xor_sync(0xffu, w, o);
        if (tid == 0) sh[0] = w;
    }
    __syncthreads();
    float r = sh[0];
    __syncthreads();
    return r;
}

__device__ __forceinline__ float blockReduceMax256(float v, float* sh) {
    int tid = threadIdx.x;
    #pragma unroll
    for (int o = 16; o > 0; o >>= 1) v = fmaxf(v, __shfl_xor_sync(0xffffffffu, v, o));
    if ((tid & 31) == 0) sh[tid >> 5] = v;
    __syncthreads();
    if (tid < 8) {
        float w = sh[tid];
        #pragma unroll
        for (int o = 4; o > 0; o >>= 1) w = fmaxf(w, __shfl_xor_sync(0xffu, w, o));
        if (tid == 0) sh[0] = w;
    }
    __syncthreads();
    float r = sh[0];
    __syncthreads();
    return r;
}

// ---------------------------------------------------------------------------
// LayerNorm. One block per row (256 threads, D=2048 -> 8 floats/thread).
// Optionally also writes x2 = h + x (for LN1).
// ---------------------------------------------------------------------------
__global__ __launch_bounds__(256) void ln_kernel(
    const float* __restrict__ x, const float* __restrict__ scale,
    const float* __restrict__ bias, float* __restrict__ out_h,
    float* __restrict__ out_x2)
{
    __shared__ float sh[8];
    int row = blockIdx.x;
    int tid = threadIdx.x;
    const float4* xr = (const float4*)(x + (size_t)row * D);
    float4 v0 = xr[tid];
    float4 v1 = xr[tid + 256];
    float s = v0.x + v0.y + v0.z + v0.w + v1.x + v1.y + v1.z + v1.w;
    float mean = blockReduceSum256(s, sh) * (1.0f / (float)D);

    float d0x = v0.x - mean, d0y = v0.y - mean, d0z = v0.z - mean, d0w = v0.w - mean;
    float d1x = v1.x - mean, d1y = v1.y - mean, d1z = v1.z - mean, d1w = v1.w - mean;
    float ss = d0x*d0x + d0y*d0y + d0z*d0z + d0w*d0w
             + d1x*d1x + d1y*d1y + d1z*d1z + d1w*d1w;
    float var = blockReduceSum256(ss, sh) * (1.0f / (float)D);
    float inv = rsqrtf(var + 1e-5f);

    const float4* sc = (const float4*)scale;
    const float4* bi = (const float4*)bias;
    float4 s0 = sc[tid], s1 = sc[tid + 256];
    float4 b0 = bi[tid], b1 = bi[tid + 256];

    float4 h0, h1;
    h0.x = d0x * inv * s0.x + b0.x;  h0.y = d0y * inv * s0.y + b0.y;
    h0.z = d0z * inv * s0.z + b0.z;  h0.w = d0w * inv * s0.w + b0.w;
    h1.x = d1x * inv * s1.x + b1.x;  h1.y = d1y * inv * s1.y + b1.y;
    h1.z = d1z * inv * s1.z + b1.z;  h1.w = d1w * inv * s1.w + b1.w;

    float4* hr = (float4*)(out_h + (size_t)row * D);
    hr[tid] = h0;
    hr[tid + 256] = h1;

    if (out_x2) {
        float4 e0, e1;
        e0.x = h0.x + v0.x; e0.y = h0.y + v0.y; e0.z = h0.z + v0.z; e0.w = h0.w + v0.w;
        e1.x = h1.x + v1.x; e1.y = h1.y + v1.y; e1.z = h1.z + v1.z; e1.w = h1.w + v1.w;
        float4* xr2 = (float4*)(out_x2 + (size_t)row * D);
        xr2[tid] = e0;
        xr2[tid + 256] = e1;
    }
}

// ---------------------------------------------------------------------------
// SGEMM: C[M,N] = A[M,K] @ B[K,N], fp32.
// 128x128 block tile, BK=8, 256 threads, 8x8 micro-tile (split 4+4).
// mode 0: C = acc
// mode 1: C = relu(acc + bias[col])
// mode 2: C = acc + bias[col] + res[row*N+col]
// ---------------------------------------------------------------------------
__global__ __launch_bounds__(256) void sgemm_kernel(
    const float* __restrict__ A, const float* __restrict__ B,
    float* __restrict__ C, const float* __restrict__ bias,
    const float* __restrict__ res, int M, int N, int K, int mode)
{
    __shared__ float As[8][128];
    __shared__ float Bs[8][128];

    int tid = threadIdx.x;
    int bx = blockIdx.x, by = blockIdx.y;
    int tx = tid & 15, ty = tid >> 4;

    int arow = tid >> 1;           // 0..127
    int acol = (tid & 1) * 4;      // 0 or 4
    const float* Aptr = A + (size_t)(by * 128 + arow) * K + acol;

    int brow = tid >> 5;           // 0..7
    int bcol = (tid & 31) * 4;     // 0..124
    const float* Bptr = B + (size_t)brow * N + (size_t)bx * 128 + bcol;

    float acc[8][8];
    #pragma unroll
    for (int i = 0; i < 8; i++)
        #pragma unroll
        for (int j = 0; j < 8; j++) acc[i][j] = 0.0f;

    for (int k0 = 0; k0 < K; k0 += 8) {
        float4 av = *(const float4*)(Aptr + k0);
        float4 bv = *(const float4*)(Bptr + (size_t)k0 * N);
        As[acol + 0][arow] = av.x;
        As[acol + 1][arow] = av.y;
        As[acol + 2][arow] = av.z;
        As[acol + 3][arow] = av.w;
        *(float4*)&Bs[brow][bcol] = bv;
        __syncthreads();

        #pragma unroll
        for (int kk = 0; kk < 8; kk++) {
            float a[8], b[8];
            *(float4*)(a)     = *(const float4*)&As[kk][ty * 4];
            *(float4*)(a + 4) = *(const float4*)&As[kk][ty * 4 + 64];
            *(float4*)(b)     = *(const float4*)&Bs[kk][tx * 4];
            *(float4*)(b + 4) = *(const float4*)&Bs[kk][tx * 4 + 64];
            #pragma unroll
            for (int i = 0; i < 8; i++)
                #pragma unroll
                for (int j = 0; j < 8; j++)
                    acc[i][j] += a[i] * b[j];
        }
        __syncthreads();
    }

    #pragma unroll
    for (int i = 0; i < 8; i++) {
        int rl = (i < 4) ? (ty * 4 + i) : (64 + ty * 4 + (i - 4));
        size_t r = (size_t)(by * 128 + rl);
        #pragma unroll
        for (int jh = 0; jh < 2; jh++) {
            int c = bx * 128 + tx * 4 + jh * 64;
            float4 o;
            o.x = acc[i][jh * 4 + 0];
            o.y = acc[i][jh * 4 + 1];
            o.z = acc[i][jh * 4 + 2];
            o.w = acc[i][jh * 4 + 3];
            if (mode >= 1) {
                float4 bb = *(const float4*)(bias + c);
                o.x += bb.x; o.y += bb.y; o.z += bb.z; o.w += bb.w;
            }
            if (mode == 1) {
                o.x = fmaxf(o.x, 0.0f); o.y = fmaxf(o.y, 0.0f);
                o.z = fmaxf(o.z, 0.0f); o.w = fmaxf(o.w, 0.0f);
            }
            if (mode == 2) {
                float4 rr = *(const float4*)(res + r * (size_t)N + c);
                o.x += rr.x; o.y += rr.y; o.z += rr.z; o.w += rr.w;
            }
            *(float4*)(C + r * (size_t)N + c) = o;
        }
    }
}

// ---------------------------------------------------------------------------
// Attention scores: raw scores[b,h,i,j] = (1/sqrt(D)) * sum_d Q(b,i,h,d)K(b,j,h,d)
// NT GEMM per (b,h): [1024x64] x [1024x64]^T. Block tile 128x128, chunks of 16 d.
// Writes RAW scores into the attn output region (softmax pass follows).
// ---------------------------------------------------------------------------
__global__ __launch_bounds__(256) void scores_kernel(
    const float* __restrict__ q, const float* __restrict__ k,
    float* __restrict__ attn)
{
    __shared__ float Qs[128][17];
    __shared__ float Ks[128][17];

    int bh = blockIdx.z;
    int b = bh >> 5;       // / NHEADS
    int h = bh & 31;
    int ib = blockIdx.y * 128, jb = blockIdx.x * 128;
    int tid = threadIdx.x;
    int tx = tid & 15, ty = tid >> 4;

    const float* qbase = q + (size_t)(b * SEQ) * D + h * HDIM;
    const float* kbase = k + (size_t)(b * SEQ) * D + h * HDIM;

    float acc[8][8];
    #pragma unroll
    for (int i = 0; i < 8; i++)
        #pragma unroll
        for (int j = 0; j < 8; j++) acc[i][j] = 0.0f;

    for (int d0 = 0; d0 < HDIM; d0 += 16) {
        #pragma unroll
        for (int l = 0; l < 2; l++) {
            int idx = tid + l * 256;      // 0..511
            int r = idx >> 2;             // 0..127
            int c4 = (idx & 3) * 4;       // 0,4,8,12
            float4 v = *(const float4*)(qbase + (size_t)(ib + r) * D + d0 + c4);
            Qs[r][c4 + 0] = v.x; Qs[r][c4 + 1] = v.y;
            Qs[r][c4 + 2] = v.z; Qs[r][c4 + 3] = v.w;
            float4 w = *(const float4*)(kbase + (size_t)(jb + r) * D + d0 + c4);
            Ks[r][c4 + 0] = w.x; Ks[r][c4 + 1] = w.y;
            Ks[r][c4 + 2] = w.z; Ks[r][c4 + 3] = w.w;
        }
        __syncthreads();

        #pragma unroll
        for (int d = 0; d < 16; d++) {
            float a[8], bb[8];
            #pragma unroll
            for (int ii = 0; ii < 4; ii++) {
                a[ii]      = Qs[ty * 4 + ii][d];
                a[4 + ii]  = Qs[64 + ty * 4 + ii][d];
                bb[ii]     = Ks[tx * 4 + ii][d];
                bb[4 + ii] = Ks[64 + tx * 4 + ii][d];
            }
            #pragma unroll
            for (int i = 0; i < 8; i++)
                #pragma unroll
                for (int j = 0; j < 8; j++)
                    acc[i][j] += a[i] * bb[j];
        }
        __syncthreads();
    }

    const float scl = rsqrtf((float)D);
    float* out = attn + (size_t)(b * NHEADS + h) * SEQ * SEQ;
    #pragma unroll
    for (int i = 0; i < 8; i++) {
        int rl = (i < 4) ? (ty * 4 + i) : (64 + ty * 4 + (i - 4));
        size_t r = (size_t)(ib + rl);
        #pragma unroll
        for (int jh = 0; jh < 2; jh++) {
            int c = jb + tx * 4 + jh * 64;
            float4 o;
            o.x = acc[i][jh * 4 + 0] * scl;
            o.y = acc[i][jh * 4 + 1] * scl;
            o.z = acc[i][jh * 4 + 2] * scl;
            o.w = acc[i][jh * 4 + 3] * scl;
            *(float4*)(out + r * SEQ + c) = o;
        }
    }
}

// ---------------------------------------------------------------------------
// In-place row softmax over last dim (SEQ=1024). One block (256 thr) per row.
// ---------------------------------------------------------------------------
__global__ __launch_bounds__(256) void softmax_kernel(float* __restrict__ attn)
{
    __shared__ float sh[8];
    size_t row = blockIdx.x;
    float4* p = (float4*)(attn + row * SEQ);
    int tid = threadIdx.x;
    float4 v = p[tid];
    float m = fmaxf(fmaxf(v.x, v.y), fmaxf(v.z, v.w));
    m = blockReduceMax256(m, sh);
    float4 e;
    e.x = __expf(v.x - m);
    e.y = __expf(v.y - m);
    e.z = __expf(v.z - m);
    e.w = __expf(v.w - m);
    float s = e.x + e.y + e.z + e.w;
    s = blockReduceSum256(s, sh);
    float inv = 1.0f / s;
    e.x *= inv; e.y *= inv; e.z *= inv; e.w *= inv;
    p[tid] = e;
}

// ---------------------------------------------------------------------------
// Launch
// ---------------------------------------------------------------------------
extern "C" void kernel_launch(void* const* d_in, const int* in_sizes, int n_in,
                              void* d_out, int out_size)
{
    const float* x     = (const float*)d_in[0];
    const float* Wq    = (const float*)d_in[1];
    const float* Wk    = (const float*)d_in[2];
    /* d_in[3] = Wv: DEAD in the reference (attended values are discarded). */
    const float* ln1_s = (const float*)d_in[4];
    const float* ln1_b = (const float*)d_in[5];
    const float* ln2_s = (const float*)d_in[6];
    const float* ln2_b = (const float*)d_in[7];
    const float* ff1_w = (const float*)d_in[8];
    const float* ff1_b = (const float*)d_in[9];
    const float* ff2_w = (const float*)d_in[10];
    const float* ff2_b = (const float*)d_in[11];

    float* out  = (float*)d_out;                       // [4,1024,2048]
    float* attn = out + (size_t)NROWS * D;             // [4,32,1024,1024]

    float *h, *x2, *q, *k, *h2, *t;
    cudaGetSymbolAddress((void**)&h,  g_h);
    cudaGetSymbolAddress((void**)&x2, g_x2);
    cudaGetSymbolAddress((void**)&q,  g_q);
    cudaGetSymbolAddress((void**)&k,  g_k);
    cudaGetSymbolAddress((void**)&h2, g_h2);
    cudaGetSymbolAddress((void**)&t,  g_t);

    dim3 gg(D / 128, NROWS / 128);   // (16, 32)

    // LN1: h = LN(x), x2 = h + x
    ln_kernel<<<NROWS, 256>>>(x, ln1_s, ln1_b, h, x2);
    // q = h @ Wq ; k = h @ Wk   (Wv skipped — dead code in reference)
    sgemm_kernel<<<gg, 256>>>(h, Wq, q, nullptr, nullptr, NROWS, D, D, 0);
    sgemm_kernel<<<gg, 256>>>(h, Wk, k, nullptr, nullptr, NROWS, D, D, 0);
    // raw scores -> attn region
    scores_kernel<<<dim3(SEQ / 128, SEQ / 128, NBATCH * NHEADS), 256>>>(q, k, attn);
    // softmax in place
    softmax_kernel<<<NBATCH * NHEADS * SEQ, 256>>>(attn);
    // LN2 on x2
    ln_kernel<<<NROWS, 256>>>(x2, ln2_s, ln2_b, h2, nullptr);
    // t = relu(h2 @ ff1_w + ff1_b)
    sgemm_kernel<<<gg, 256>>>(h2, ff1_w, t, ff1_b, nullptr, NROWS, D, D, 1);
    // out = t @ ff2_w + ff2_b + x2
    sgemm_kernel<<<gg, 256>>>(t, ff2_w, out, ff2_b, x2, NROWS, D, D, 2);
}

// round 3
// speedup vs baseline: 2.8462x; 2.8462x over previous
#include <cuda_runtime.h>
#include <cstdint>

#define D 2048
#define NROWS 4096     // B*S
#define NHEADS 32
#define HDIM 64
#define SEQ 1024
#define NBATCH 4

// Scratch (allocation-free rule: __device__ globals)
__device__ float g_h  [NROWS * D];   // tf32-rounded LN1 output
__device__ float g_x2 [NROWS * D];   // exact h + x residual
__device__ float g_q  [NROWS * D];   // tf32-rounded q
__device__ float g_k  [NROWS * D];   // tf32-rounded k
__device__ float g_h2 [NROWS * D];   // tf32-rounded LN2 output
__device__ float g_t  [NROWS * D];   // tf32-rounded relu(ff1)
__device__ float g_wqt[D * D];       // transposed + tf32-rounded weights [n][k]
__device__ float g_wkt[D * D];
__device__ float g_f1t[D * D];
__device__ float g_f2t[D * D];

// ===========================================================================
// Helpers
// ===========================================================================
__device__ __forceinline__ uint32_t smem_u32(const void* p) {
    uint32_t a;
    asm("{ .reg .u64 t; cvta.to.shared.u64 t, %1; cvt.u32.u64 %0, t; }" : "=r"(a) : "l"(p));
    return a;
}
__device__ __forceinline__ float tf32r(float x) {
    uint32_t u;
    asm("cvt.rna.tf32.f32 %0, %1;" : "=r"(u) : "f"(x));
    return __uint_as_float(u);
}
// D(16x8) += A(16x8,row) * B(8x8,col) ; tf32 inputs as fp32-bit registers
__device__ __forceinline__ void mma_tf32(float* c, uint32_t a0, uint32_t a1,
                                         uint32_t a2, uint32_t a3,
                                         uint32_t b0, uint32_t b1) {
    asm volatile(
        "mma.sync.aligned.m16n8k8.row.col.f32.tf32.tf32.f32 "
        "{%0,%1,%2,%3}, {%4,%5,%6,%7}, {%8,%9}, {%0,%1,%2,%3};"
        : "+f"(c[0]), "+f"(c[1]), "+f"(c[2]), "+f"(c[3])
        : "r"(a0), "r"(a1), "r"(a2), "r"(a3), "r"(b0), "r"(b1));
}
#define CP_ASYNC16(smem_addr, gptr) \
    asm volatile("cp.async.cg.shared.global [%0], [%1], 16;" :: "r"(smem_addr), "l"(gptr) : "memory")
#define CP_COMMIT() asm volatile("cp.async.commit_group;" ::: "memory")
#define CP_WAIT1()  asm volatile("cp.async.wait_group 1;" ::: "memory")

// ===========================================================================
// Block reductions (256 threads)
// ===========================================================================
__device__ __forceinline__ float blockReduceSum256(float v, float* sh) {
    int tid = threadIdx.x;
    #pragma unroll
    for (int o = 16; o > 0; o >>= 1) v += __shfl_xor_sync(0xffffffffu, v, o);
    if ((tid & 31) == 0) sh[tid >> 5] = v;
    __syncthreads();
    if (tid < 8) {
        float w = sh[tid];
        #pragma unroll
        for (int o = 4; o > 0; o >>= 1) w += __shfl_xor_sync(0xffu, w, o);
        if (tid == 0) sh[0] = w;
    }
    __syncthreads();
    float r = sh[0];
    __syncthreads();
    return r;
}
__device__ __forceinline__ float blockReduceMax256(float v, float* sh) {
    int tid = threadIdx.x;
    #pragma unroll
    for (int o = 16; o > 0; o >>= 1) v = fmaxf(v, __shfl_xor_sync(0xffffffffu, v, o));
    if ((tid & 31) == 0) sh[tid >> 5] = v;
    __syncthreads();
    if (tid < 8) {
        float w = sh[tid];
        #pragma unroll
        for (int o = 4; o > 0; o >>= 1) w = fmaxf(w, __shfl_xor_sync(0xffu, w, o));
        if (tid == 0) sh[0] = w;
    }
    __syncthreads();
    float r = sh[0];
    __syncthreads();
    return r;
}

// ===========================================================================
// LayerNorm. One block per row. out_h = tf32-rounded LN (feeds GEMMs only);
// out_x2 (optional) = exact h + x.
// ===========================================================================
__global__ __launch_bounds__(256) void ln_kernel(
    const float* __restrict__ x, const float* __restrict__ scale,
    const float* __restrict__ bias, float* __restrict__ out_h,
    float* __restrict__ out_x2)
{
    __shared__ float sh[8];
    int row = blockIdx.x;
    int tid = threadIdx.x;
    const float4* xr = (const float4*)(x + (size_t)row * D);
    float4 v0 = xr[tid];
    float4 v1 = xr[tid + 256];
    float s = v0.x + v0.y + v0.z + v0.w + v1.x + v1.y + v1.z + v1.w;
    float mean = blockReduceSum256(s, sh) * (1.0f / (float)D);

    float d0x = v0.x - mean, d0y = v0.y - mean, d0z = v0.z - mean, d0w = v0.w - mean;
    float d1x = v1.x - mean, d1y = v1.y - mean, d1z = v1.z - mean, d1w = v1.w - mean;
    float ss = d0x*d0x + d0y*d0y + d0z*d0z + d0w*d0w
             + d1x*d1x + d1y*d1y + d1z*d1z + d1w*d1w;
    float var = blockReduceSum256(ss, sh) * (1.0f / (float)D);
    float inv = rsqrtf(var + 1e-5f);

    const float4* sc = (const float4*)scale;
    const float4* bi = (const float4*)bias;
    float4 s0 = sc[tid], s1 = sc[tid + 256];
    float4 b0 = bi[tid], b1 = bi[tid + 256];

    float4 h0, h1;
    h0.x = d0x * inv * s0.x + b0.x;  h0.y = d0y * inv * s0.y + b0.y;
    h0.z = d0z * inv * s0.z + b0.z;  h0.w = d0w * inv * s0.w + b0.w;
    h1.x = d1x * inv * s1.x + b1.x;  h1.y = d1y * inv * s1.y + b1.y;
    h1.z = d1z * inv * s1.z + b1.z;  h1.w = d1w * inv * s1.w + b1.w;

    float4 r0, r1;
    r0.x = tf32r(h0.x); r0.y = tf32r(h0.y); r0.z = tf32r(h0.z); r0.w = tf32r(h0.w);
    r1.x = tf32r(h1.x); r1.y = tf32r(h1.y); r1.z = tf32r(h1.z); r1.w = tf32r(h1.w);
    float4* hr = (float4*)(out_h + (size_t)row * D);
    hr[tid] = r0;
    hr[tid + 256] = r1;

    if (out_x2) {
        float4 e0, e1;
        e0.x = h0.x + v0.x; e0.y = h0.y + v0.y; e0.z = h0.z + v0.z; e0.w = h0.w + v0.w;
        e1.x = h1.x + v1.x; e1.y = h1.y + v1.y; e1.z = h1.z + v1.z; e1.w = h1.w + v1.w;
        float4* xr2 = (float4*)(out_x2 + (size_t)row * D);
        xr2[tid] = e0;
        xr2[tid + 256] = e1;
    }
}

// ===========================================================================
// Weight transpose + tf32 round: Wt[n][k] = tf32(W[k][n]).
// ===========================================================================
__global__ __launch_bounds__(256) void transpose_round_kernel(
    const float* __restrict__ W, float* __restrict__ Wt)
{
    __shared__ float t[32][33];
    int bx = blockIdx.x * 32;
    int by = blockIdx.y * 32;
    int tx = threadIdx.x & 31;
    int ty = threadIdx.x >> 5;
    #pragma unroll
    for (int i = 0; i < 4; i++)
        t[ty + i * 8][tx] = W[(size_t)(by + ty + i * 8) * D + bx + tx];
    __syncthreads();
    #pragma unroll
    for (int i = 0; i < 4; i++)
        Wt[(size_t)(bx + ty + i * 8) * D + by + tx] = tf32r(t[tx][ty + i * 8]);
}

// ===========================================================================
// tf32 mma.sync GEMM: C[4096,2048] = A[4096,2048] @ Bt[2048,2048]^T
// (Bt K-major: Bt[n][k]). CTA 128x128, BK=32, 3-stage cp.async.
// 8 warps: warp_m = wid&1 (64 rows), warp_n = wid>>1 (32 cols).
// mode 0: C = tf32_round(acc)                       (q/k — consumed by mma)
// mode 1: C = tf32_round(relu(acc + bias[col]))
// mode 2: C = acc + bias[col] + res[row][col]        (exact fp32 out)
// ===========================================================================
#define BM 128
#define BN 128
#define BK 32
#define GSTAGES 3
#define APAD 36                          // padded row stride (words)
#define TILE_WORDS (128 * APAD)          // 4608
#define STAGE_WORDS (2 * TILE_WORDS)     // 9216
#define GEMM_SMEM (GSTAGES * STAGE_WORDS * 4)  // 110592 B

__global__ __launch_bounds__(256) void gemm_tf32_kernel(
    const float* __restrict__ A, const float* __restrict__ Bt,
    float* __restrict__ C, const float* __restrict__ bias,
    const float* __restrict__ res, int mode)
{
    extern __shared__ float smem[];
    const int K = D, N = D;
    uint32_t sb = smem_u32(smem);
    int tid = threadIdx.x;
    int wid = tid >> 5;
    int lane = tid & 31;
    int g4 = lane >> 2;      // 0..7
    int t4 = lane & 3;       // 0..3
    int m0 = blockIdx.y * BM;
    int n0 = blockIdx.x * BN;
    int mbase = (wid & 1) * 64;
    int nbase = (wid >> 1) * 32;

    int lrow = tid >> 3;            // 0..31? no: tid/8 -> 0..31  (for loads)
    // load mapping: 1024 float4 chunks per tile; 256 threads x 4 chunks
    // chunk g: row = g>>3 (0..127), col granule = g&7

    float acc[4][4][4];
    #pragma unroll
    for (int mi = 0; mi < 4; mi++)
        #pragma unroll
        for (int ni = 0; ni < 4; ni++)
            #pragma unroll
            for (int r = 0; r < 4; r++) acc[mi][ni][r] = 0.0f;

    const int NCHUNK = K / BK;   // 64

    // ---- async load of one stage
    auto load_stage = [&](int kc, int st) {
        uint32_t s_a = sb + (uint32_t)st * STAGE_WORDS * 4;
        uint32_t s_b = s_a + TILE_WORDS * 4;
        #pragma unroll
        for (int i = 0; i < 4; i++) {
            int g = tid + i * 256;          // 0..1023
            int r = g >> 3, c = g & 7;
            const float* ga = A  + (size_t)(m0 + r) * K + kc * BK + c * 4;
            const float* gb = Bt + (size_t)(n0 + r) * K + kc * BK + c * 4;
            uint32_t off = (uint32_t)(r * APAD + c * 4) * 4;
            CP_ASYNC16(s_a + off, ga);
            CP_ASYNC16(s_b + off, gb);
        }
    };

    load_stage(0, 0); CP_COMMIT();
    load_stage(1, 1); CP_COMMIT();

    for (int kc = 0; kc < NCHUNK; kc++) {
        int st = kc % GSTAGES;
        CP_WAIT1();
        __syncthreads();
        if (kc + 2 < NCHUNK) load_stage(kc + 2, (kc + 2) % GSTAGES);
        CP_COMMIT();

        const float* As = smem + (size_t)st * STAGE_WORDS;
        const float* Bs = As + TILE_WORDS;

        #pragma unroll
        for (int s = 0; s < 4; s++) {
            uint32_t afr[4][4];
            #pragma unroll
            for (int mi = 0; mi < 4; mi++) {
                int row = mbase + mi * 16 + g4;
                int col = s * 8 + t4;
                afr[mi][0] = __float_as_uint(As[row * APAD + col]);
                afr[mi][1] = __float_as_uint(As[(row + 8) * APAD + col]);
                afr[mi][2] = __float_as_uint(As[row * APAD + col + 4]);
                afr[mi][3] = __float_as_uint(As[(row + 8) * APAD + col + 4]);
            }
            uint32_t bfr[4][2];
            #pragma unroll
            for (int ni = 0; ni < 4; ni++) {
                int n = nbase + ni * 8 + g4;
                int k = s * 8 + t4;
                bfr[ni][0] = __float_as_uint(Bs[n * APAD + k]);
                bfr[ni][1] = __float_as_uint(Bs[n * APAD + k + 4]);
            }
            #pragma unroll
            for (int mi = 0; mi < 4; mi++)
                #pragma unroll
                for (int ni = 0; ni < 4; ni++)
                    mma_tf32(acc[mi][ni], afr[mi][0], afr[mi][1], afr[mi][2],
                             afr[mi][3], bfr[ni][0], bfr[ni][1]);
        }
    }

    // ---- epilogue
    #pragma unroll
    for (int mi = 0; mi < 4; mi++) {
        int r0 = m0 + mbase + mi * 16 + g4;
        int r1 = r0 + 8;
        #pragma unroll
        for (int ni = 0; ni < 4; ni++) {
            int c = n0 + nbase + ni * 8 + t4 * 2;
            float v00 = acc[mi][ni][0], v01 = acc[mi][ni][1];
            float v10 = acc[mi][ni][2], v11 = acc[mi][ni][3];
            if (mode >= 1) {
                float b0v = bias[c], b1v = bias[c + 1];
                v00 += b0v; v01 += b1v; v10 += b0v; v11 += b1v;
            }
            if (mode == 1) {
                v00 = tf32r(fmaxf(v00, 0.0f)); v01 = tf32r(fmaxf(v01, 0.0f));
                v10 = tf32r(fmaxf(v10, 0.0f)); v11 = tf32r(fmaxf(v11, 0.0f));
            } else if (mode == 0) {
                v00 = tf32r(v00); v01 = tf32r(v01);
                v10 = tf32r(v10); v11 = tf32r(v11);
            } else {
                const float2* rp0 = (const float2*)(res + (size_t)r0 * N + c);
                const float2* rp1 = (const float2*)(res + (size_t)r1 * N + c);
                float2 rv0 = *rp0, rv1 = *rp1;
                v00 += rv0.x; v01 += rv0.y; v10 += rv1.x; v11 += rv1.y;
            }
            float2 o0; o0.x = v00; o0.y = v01;
            float2 o1; o1.x = v10; o1.y = v11;
            *(float2*)(C + (size_t)r0 * N + c) = o0;
            *(float2*)(C + (size_t)r1 * N + c) = o1;
        }
    }
}

// ===========================================================================
// Attention scores via tf32 mma: raw scores -> attn region.
// Per (b,h): [1024x64] @ [1024x64]^T. CTA tile 128x128, K=64 one-shot.
// ===========================================================================
#define SPAD 68
#define SC_SMEM (2 * 128 * SPAD * 4)   // 69632 B

__global__ __launch_bounds__(256) void scores_kernel(
    const float* __restrict__ q, const float* __restrict__ k,
    float* __restrict__ attn)
{
    extern __shared__ float smem[];
    float* Qs = smem;                    // [128][SPAD]
    float* Ks = smem + 128 * SPAD;       // [128][SPAD]

    int bh = blockIdx.z;
    int b = bh >> 5;
    int h = bh & 31;
    int ib = blockIdx.y * 128, jb = blockIdx.x * 128;
    int tid = threadIdx.x;
    int wid = tid >> 5;
    int lane = tid & 31;
    int g4 = lane >> 2, t4 = lane & 3;
    int mbase = (wid & 1) * 64;
    int nbase = (wid >> 1) * 32;

    const float* qbase = q + (size_t)(b * SEQ) * D + h * HDIM;
    const float* kbase = k + (size_t)(b * SEQ) * D + h * HDIM;

    // load tiles: 128 rows x 64 cols = 16 float4/row; 2048 chunks per tile
    #pragma unroll
    for (int i = 0; i < 8; i++) {
        int idx = tid + i * 256;         // 0..2047
        int r = idx >> 4;
        int c4 = (idx & 15) * 4;
        float4 v = *(const float4*)(qbase + (size_t)(ib + r) * D + c4);
        *(float4*)&Qs[r * SPAD + c4] = v;
        float4 w = *(const float4*)(kbase + (size_t)(jb + r) * D + c4);
        *(float4*)&Ks[r * SPAD + c4] = w;
    }
    __syncthreads();

    float acc[4][4][4];
    #pragma unroll
    for (int mi = 0; mi < 4; mi++)
        #pragma unroll
        for (int ni = 0; ni < 4; ni++)
            #pragma unroll
            for (int r = 0; r < 4; r++) acc[mi][ni][r] = 0.0f;

    #pragma unroll
    for (int s = 0; s < 8; s++) {
        uint32_t afr[4][4];
        #pragma unroll
        for (int mi = 0; mi < 4; mi++) {
            int row = mbase + mi * 16 + g4;
            int col = s * 8 + t4;
            afr[mi][0] = __float_as_uint(Qs[row * SPAD + col]);
            afr[mi][1] = __float_as_uint(Qs[(row + 8) * SPAD + col]);
            afr[mi][2] = __float_as_uint(Qs[row * SPAD + col + 4]);
            afr[mi][3] = __float_as_uint(Qs[(row + 8) * SPAD + col + 4]);
        }
        uint32_t bfr[4][2];
        #pragma unroll
        for (int ni = 0; ni < 4; ni++) {
            int n = nbase + ni * 8 + g4;
            int kk = s * 8 + t4;
            bfr[ni][0] = __float_as_uint(Ks[n * SPAD + kk]);
            bfr[ni][1] = __float_as_uint(Ks[n * SPAD + kk + 4]);
        }
        #pragma unroll
        for (int mi = 0; mi < 4; mi++)
            #pragma unroll
            for (int ni = 0; ni < 4; ni++)
                mma_tf32(acc[mi][ni], afr[mi][0], afr[mi][1], afr[mi][2],
                         afr[mi][3], bfr[ni][0], bfr[ni][1]);
    }

    const float scl = rsqrtf((float)D);
    float* out = attn + (size_t)(b * NHEADS + h) * SEQ * SEQ;
    #pragma unroll
    for (int mi = 0; mi < 4; mi++) {
        int r0 = ib + mbase + mi * 16 + g4;
        int r1 = r0 + 8;
        #pragma unroll
        for (int ni = 0; ni < 4; ni++) {
            int c = jb + nbase + ni * 8 + t4 * 2;
            float2 o0, o1;
            o0.x = acc[mi][ni][0] * scl; o0.y = acc[mi][ni][1] * scl;
            o1.x = acc[mi][ni][2] * scl; o1.y = acc[mi][ni][3] * scl;
            *(float2*)(out + (size_t)r0 * SEQ + c) = o0;
            *(float2*)(out + (size_t)r1 * SEQ + c) = o1;
        }
    }
}

// ===========================================================================
// In-place row softmax over last dim (SEQ=1024).
// ===========================================================================
__global__ __launch_bounds__(256) void softmax_kernel(float* __restrict__ attn)
{
    __shared__ float sh[8];
    size_t row = blockIdx.x;
    float4* p = (float4*)(attn + row * SEQ);
    int tid = threadIdx.x;
    float4 v = p[tid];
    float m = fmaxf(fmaxf(v.x, v.y), fmaxf(v.z, v.w));
    m = blockReduceMax256(m, sh);
    float4 e;
    e.x = __expf(v.x - m);
    e.y = __expf(v.y - m);
    e.z = __expf(v.z - m);
    e.w = __expf(v.w - m);
    float s = e.x + e.y + e.z + e.w;
    s = blockReduceSum256(s, sh);
    float inv = 1.0f / s;
    e.x *= inv; e.y *= inv; e.z *= inv; e.w *= inv;
    p[tid] = e;
}

// ===========================================================================
// Launch
// ===========================================================================
extern "C" void kernel_launch(void* const* d_in, const int* in_sizes, int n_in,
                              void* d_out, int out_size)
{
    const float* x     = (const float*)d_in[0];
    const float* Wq    = (const float*)d_in[1];
    const float* Wk    = (const float*)d_in[2];
    /* d_in[3] = Wv: DEAD in the reference (attended values are discarded). */
    const float* ln1_s = (const float*)d_in[4];
    const float* ln1_b = (const float*)d_in[5];
    const float* ln2_s = (const float*)d_in[6];
    const float* ln2_b = (const float*)d_in[7];
    const float* ff1_w = (const float*)d_in[8];
    const float* ff1_b = (const float*)d_in[9];
    const float* ff2_w = (const float*)d_in[10];
    const float* ff2_b = (const float*)d_in[11];

    float* out  = (float*)d_out;                       // [4,1024,2048]
    float* attn = out + (size_t)NROWS * D;             // [4,32,1024,1024]

    float *h, *x2, *q, *k, *h2, *t, *wqt, *wkt, *f1t, *f2t;
    cudaGetSymbolAddress((void**)&h,   g_h);
    cudaGetSymbolAddress((void**)&x2,  g_x2);
    cudaGetSymbolAddress((void**)&q,   g_q);
    cudaGetSymbolAddress((void**)&k,   g_k);
    cudaGetSymbolAddress((void**)&h2,  g_h2);
    cudaGetSymbolAddress((void**)&t,   g_t);
    cudaGetSymbolAddress((void**)&wqt, g_wqt);
    cudaGetSymbolAddress((void**)&wkt, g_wkt);
    cudaGetSymbolAddress((void**)&f1t, g_f1t);
    cudaGetSymbolAddress((void**)&f2t, g_f2t);

    static int attr_done = 0;
    cudaFuncSetAttribute(gemm_tf32_kernel,
                         cudaFuncAttributeMaxDynamicSharedMemorySize, GEMM_SMEM);
    cudaFuncSetAttribute(scores_kernel,
                         cudaFuncAttributeMaxDynamicSharedMemorySize, SC_SMEM);
    (void)attr_done;

    dim3 tg(D / 32, D / 32);                 // (64, 64)
    dim3 gg(D / BN, NROWS / BM);             // (16, 32)

    // Transpose + tf32-round the 4 live weight matrices
    transpose_round_kernel<<<tg, 256>>>(Wq,    wqt);
    transpose_round_kernel<<<tg, 256>>>(Wk,    wkt);
    transpose_round_kernel<<<tg, 256>>>(ff1_w, f1t);
    transpose_round_kernel<<<tg, 256>>>(ff2_w, f2t);

    // LN1
    ln_kernel<<<NROWS, 256>>>(x, ln1_s, ln1_b, h, x2);

    // q = h @ Wq ; k = h @ Wk (tf32 mma; outputs rounded for scores mma)
    gemm_tf32_kernel<<<gg, 256, GEMM_SMEM>>>(h, wqt, q, nullptr, nullptr, 0);
    gemm_tf32_kernel<<<gg, 256, GEMM_SMEM>>>(h, wkt, k, nullptr, nullptr, 0);

    // raw scores -> attn region; softmax in place
    scores_kernel<<<dim3(SEQ / 128, SEQ / 128, NBATCH * NHEADS), 256, SC_SMEM>>>(q, k, attn);
    softmax_kernel<<<NBATCH * NHEADS * SEQ, 256>>>(attn);

    // LN2
    ln_kernel<<<NROWS, 256>>>(x2, ln2_s, ln2_b, h2, nullptr);

    // t = tf32(relu(h2 @ ff1_w + ff1_b)) ; out = t @ ff2_w + ff2_b + x2
    gemm_tf32_kernel<<<gg, 256, GEMM_SMEM>>>(h2, f1t, t, ff1_b, nullptr, 1);
    gemm_tf32_kernel<<<gg, 256, GEMM_SMEM>>>(t, f2t, out, ff2_b, x2, 2);
}

// round 4
// speedup vs baseline: 3.4755x; 1.2211x over previous
#include <cuda_runtime.h>
#include <cstdint>

#define D 2048
#define NROWS 4096     // B*S
#define NHEADS 32
#define HDIM 64
#define SEQ 1024
#define NBATCH 4

// Scratch (allocation-free rule: __device__ globals)
__device__ float g_h  [NROWS * D];       // tf32-rounded LN1 output
__device__ float g_x2 [NROWS * D];       // exact h + x residual
__device__ float g_qk [NROWS * 2 * D];   // tf32-rounded [q | k], row stride 4096
__device__ float g_h2 [NROWS * D];       // tf32-rounded LN2 output
__device__ float g_t  [NROWS * D];       // tf32-rounded relu(ff1)
__device__ float g_wqkt[2 * D * D];      // [Wq^T ; Wk^T] K-major, tf32-rounded
__device__ float g_f1t[D * D];
__device__ float g_f2t[D * D];

// ===========================================================================
// Helpers
// ===========================================================================
__device__ __forceinline__ uint32_t smem_u32(const void* p) {
    uint32_t a;
    asm("{ .reg .u64 t; cvta.to.shared.u64 t, %1; cvt.u32.u64 %0, t; }" : "=r"(a) : "l"(p));
    return a;
}
__device__ __forceinline__ float tf32r(float x) {
    uint32_t u;
    asm("cvt.rna.tf32.f32 %0, %1;" : "=r"(u) : "f"(x));
    return __uint_as_float(u);
}
__device__ __forceinline__ void mma_tf32(float* c, uint32_t a0, uint32_t a1,
                                         uint32_t a2, uint32_t a3,
                                         uint32_t b0, uint32_t b1) {
    asm volatile(
        "mma.sync.aligned.m16n8k8.row.col.f32.tf32.tf32.f32 "
        "{%0,%1,%2,%3}, {%4,%5,%6,%7}, {%8,%9}, {%0,%1,%2,%3};"
        : "+f"(c[0]), "+f"(c[1]), "+f"(c[2]), "+f"(c[3])
        : "r"(a0), "r"(a1), "r"(a2), "r"(a3), "r"(b0), "r"(b1));
}
__device__ __forceinline__ void ldsm_x4(uint32_t& r0, uint32_t& r1,
                                        uint32_t& r2, uint32_t& r3, uint32_t addr) {
    asm volatile("ldmatrix.sync.aligned.m8n8.x4.shared.b16 {%0,%1,%2,%3}, [%4];"
        : "=r"(r0), "=r"(r1), "=r"(r2), "=r"(r3) : "r"(addr));
}
#define CP_ASYNC16(smem_addr, gptr) \
    asm volatile("cp.async.cg.shared.global [%0], [%1], 16;" :: "r"(smem_addr), "l"(gptr) : "memory")
#define CP_COMMIT() asm volatile("cp.async.commit_group;" ::: "memory")
#define CP_WAIT(n)  asm volatile("cp.async.wait_group %0;" :: "n"(n) : "memory")

// ===========================================================================
// Block reductions (256 threads)
// ===========================================================================
__device__ __forceinline__ float blockReduceSum256(float v, float* sh) {
    int tid = threadIdx.x;
    #pragma unroll
    for (int o = 16; o > 0; o >>= 1) v += __shfl_xor_sync(0xffffffffu, v, o);
    if ((tid & 31) == 0) sh[tid >> 5] = v;
    __syncthreads();
    if (tid < 8) {
        float w = sh[tid];
        #pragma unroll
        for (int o = 4; o > 0; o >>= 1) w += __shfl_xor_sync(0xffu, w, o);
        if (tid == 0) sh[0] = w;
    }
    __syncthreads();
    float r = sh[0];
    __syncthreads();
    return r;
}

// ===========================================================================
// LayerNorm (unchanged from R3)
// ===========================================================================
__global__ __launch_bounds__(256) void ln_kernel(
    const float* __restrict__ x, const float* __restrict__ scale,
    const float* __restrict__ bias, float* __restrict__ out_h,
    float* __restrict__ out_x2)
{
    __shared__ float sh[8];
    int row = blockIdx.x;
    int tid = threadIdx.x;
    const float4* xr = (const float4*)(x + (size_t)row * D);
    float4 v0 = xr[tid];
    float4 v1 = xr[tid + 256];
    float s = v0.x + v0.y + v0.z + v0.w + v1.x + v1.y + v1.z + v1.w;
    float mean = blockReduceSum256(s, sh) * (1.0f / (float)D);

    float d0x = v0.x - mean, d0y = v0.y - mean, d0z = v0.z - mean, d0w = v0.w - mean;
    float d1x = v1.x - mean, d1y = v1.y - mean, d1z = v1.z - mean, d1w = v1.w - mean;
    float ss = d0x*d0x + d0y*d0y + d0z*d0z + d0w*d0w
             + d1x*d1x + d1y*d1y + d1z*d1z + d1w*d1w;
    float var = blockReduceSum256(ss, sh) * (1.0f / (float)D);
    float inv = rsqrtf(var + 1e-5f);

    const float4* sc = (const float4*)scale;
    const float4* bi = (const float4*)bias;
    float4 s0 = sc[tid], s1 = sc[tid + 256];
    float4 b0 = bi[tid], b1 = bi[tid + 256];

    float4 h0, h1;
    h0.x = d0x * inv * s0.x + b0.x;  h0.y = d0y * inv * s0.y + b0.y;
    h0.z = d0z * inv * s0.z + b0.z;  h0.w = d0w * inv * s0.w + b0.w;
    h1.x = d1x * inv * s1.x + b1.x;  h1.y = d1y * inv * s1.y + b1.y;
    h1.z = d1z * inv * s1.z + b1.z;  h1.w = d1w * inv * s1.w + b1.w;

    float4 r0, r1;
    r0.x = tf32r(h0.x); r0.y = tf32r(h0.y); r0.z = tf32r(h0.z); r0.w = tf32r(h0.w);
    r1.x = tf32r(h1.x); r1.y = tf32r(h1.y); r1.z = tf32r(h1.z); r1.w = tf32r(h1.w);
    float4* hr = (float4*)(out_h + (size_t)row * D);
    hr[tid] = r0;
    hr[tid + 256] = r1;

    if (out_x2) {
        float4 e0, e1;
        e0.x = h0.x + v0.x; e0.y = h0.y + v0.y; e0.z = h0.z + v0.z; e0.w = h0.w + v0.w;
        e1.x = h1.x + v1.x; e1.y = h1.y + v1.y; e1.z = h1.z + v1.z; e1.w = h1.w + v1.w;
        float4* xr2 = (float4*)(out_x2 + (size_t)row * D);
        xr2[tid] = e0;
        xr2[tid + 256] = e1;
    }
}

// ===========================================================================
// Weight transpose + tf32 round: Wt[n][k] = tf32(W[k][n]).
// ===========================================================================
__global__ __launch_bounds__(256) void transpose_round_kernel(
    const float* __restrict__ W, float* __restrict__ Wt)
{
    __shared__ float t[32][33];
    int bx = blockIdx.x * 32;
    int by = blockIdx.y * 32;
    int tx = threadIdx.x & 31;
    int ty = threadIdx.x >> 5;
    #pragma unroll
    for (int i = 0; i < 4; i++)
        t[ty + i * 8][tx] = W[(size_t)(by + ty + i * 8) * D + bx + tx];
    __syncthreads();
    #pragma unroll
    for (int i = 0; i < 4; i++)
        Wt[(size_t)(bx + ty + i * 8) * D + by + tx] = tf32r(t[tx][ty + i * 8]);
}

// ===========================================================================
// tf32 mma GEMM with ldmatrix fragment loads.
// C[4096, N] = A[4096, 2048] @ Bt[N, 2048]^T  (Bt K-major)
// CTA 128x128, BK=32, 3-stage cp.async. 8 warps: 64x32 warp tiles.
// mode 0: C = tf32(acc) ; mode 1: C = tf32(relu(acc+bias)) ; mode 2: exact+res
// ===========================================================================
#define BM 128
#define BN 128
#define BK 32
#define GSTAGES 3
#define APAD 36
#define TILE_WORDS (128 * APAD)
#define STAGE_WORDS (2 * TILE_WORDS)
#define STAGE_BYTES (STAGE_WORDS * 4)
#define GEMM_SMEM (GSTAGES * STAGE_BYTES)

__global__ __launch_bounds__(256) void gemm_tf32_kernel(
    const float* __restrict__ A, const float* __restrict__ Bt,
    float* __restrict__ C, const float* __restrict__ bias,
    const float* __restrict__ res, int N, int mode)
{
    extern __shared__ float smem[];
    const int K = D;
    uint32_t sb = smem_u32(smem);
    int tid = threadIdx.x;
    int wid = tid >> 5;
    int lane = tid & 31;
    int g4 = lane >> 2;
    int t4 = lane & 3;
    int m0 = blockIdx.y * BM;
    int n0 = blockIdx.x * BN;
    int mbase = (wid & 1) * 64;
    int nbase = (wid >> 1) * 32;

    // ldmatrix per-lane byte offsets (within a stage)
    uint32_t a_off = ((uint32_t)(mbase + (lane & 15)) * APAD + (lane >> 4) * 4) * 4;
    uint32_t b_off = ((uint32_t)TILE_WORDS
                   + (uint32_t)(nbase + ((lane >> 4) * 8) + (lane & 7)) * APAD
                   + ((lane >> 3) & 1) * 4) * 4;

    float acc[4][4][4];
    #pragma unroll
    for (int mi = 0; mi < 4; mi++)
        #pragma unroll
        for (int ni = 0; ni < 4; ni++)
            #pragma unroll
            for (int r = 0; r < 4; r++) acc[mi][ni][r] = 0.0f;

    const int NCHUNK = K / BK;   // 64

    auto load_stage = [&](int kc, int st) {
        uint32_t s_a = sb + (uint32_t)st * STAGE_BYTES;
        uint32_t s_b = s_a + TILE_WORDS * 4;
        #pragma unroll
        for (int i = 0; i < 4; i++) {
            int g = tid + i * 256;
            int r = g >> 3, c = g & 7;
            const float* ga = A  + (size_t)(m0 + r) * K + kc * BK + c * 4;
            const float* gb = Bt + (size_t)(n0 + r) * K + kc * BK + c * 4;
            uint32_t off = (uint32_t)(r * APAD + c * 4) * 4;
            CP_ASYNC16(s_a + off, ga);
            CP_ASYNC16(s_b + off, gb);
        }
    };

    load_stage(0, 0); CP_COMMIT();
    load_stage(1, 1); CP_COMMIT();

    for (int kc = 0; kc < NCHUNK; kc++) {
        int st = kc % GSTAGES;
        CP_WAIT(1);
        __syncthreads();
        if (kc + 2 < NCHUNK) load_stage(kc + 2, (kc + 2) % GSTAGES);
        CP_COMMIT();

        uint32_t stage = sb + (uint32_t)st * STAGE_BYTES;
        #pragma unroll
        for (int s = 0; s < 4; s++) {
            uint32_t a[4][4];
            #pragma unroll
            for (int mi = 0; mi < 4; mi++)
                ldsm_x4(a[mi][0], a[mi][1], a[mi][2], a[mi][3],
                        stage + a_off + (uint32_t)(mi * 16 * APAD + s * 8) * 4);
            uint32_t b[2][4];
            #pragma unroll
            for (int np = 0; np < 2; np++)
                ldsm_x4(b[np][0], b[np][1], b[np][2], b[np][3],
                        stage + b_off + (uint32_t)(np * 16 * APAD + s * 8) * 4);
            #pragma unroll
            for (int mi = 0; mi < 4; mi++)
                #pragma unroll
                for (int ni = 0; ni < 4; ni++)
                    mma_tf32(acc[mi][ni], a[mi][0], a[mi][1], a[mi][2], a[mi][3],
                             b[ni >> 1][(ni & 1) * 2], b[ni >> 1][(ni & 1) * 2 + 1]);
        }
    }

    // ---- epilogue
    #pragma unroll
    for (int mi = 0; mi < 4; mi++) {
        int r0 = m0 + mbase + mi * 16 + g4;
        int r1 = r0 + 8;
        #pragma unroll
        for (int ni = 0; ni < 4; ni++) {
            int c = n0 + nbase + ni * 8 + t4 * 2;
            float v00 = acc[mi][ni][0], v01 = acc[mi][ni][1];
            float v10 = acc[mi][ni][2], v11 = acc[mi][ni][3];
            if (mode >= 1) {
                float b0v = bias[c], b1v = bias[c + 1];
                v00 += b0v; v01 += b1v; v10 += b0v; v11 += b1v;
            }
            if (mode == 1) {
                v00 = tf32r(fmaxf(v00, 0.0f)); v01 = tf32r(fmaxf(v01, 0.0f));
                v10 = tf32r(fmaxf(v10, 0.0f)); v11 = tf32r(fmaxf(v11, 0.0f));
            } else if (mode == 0) {
                v00 = tf32r(v00); v01 = tf32r(v01);
                v10 = tf32r(v10); v11 = tf32r(v11);
            } else {
                const float2* rp0 = (const float2*)(res + (size_t)r0 * N + c);
                const float2* rp1 = (const float2*)(res + (size_t)r1 * N + c);
                float2 rv0 = *rp0, rv1 = *rp1;
                v00 += rv0.x; v01 += rv0.y; v10 += rv1.x; v11 += rv1.y;
            }
            float2 o0; o0.x = v00; o0.y = v01;
            float2 o1; o1.x = v10; o1.y = v11;
            *(float2*)(C + (size_t)r0 * N + c) = o0;
            *(float2*)(C + (size_t)r1 * N + c) = o1;
        }
    }
}

// ===========================================================================
// FUSED attention scores + softmax.
// CTA = 32 query rows x all 1024 keys for one (b,h). 256 threads, 8 warps:
// 2 M-warps (16 rows) x 4 N-warps (32 cols per 128-key chunk).
// K streamed in 8 chunks of 128 keys (double-buffered cp.async).
// Full row of scores lives in registers -> softmax -> single write.
// ===========================================================================
#define SC_ROWS 32
#define SC_PAD 68
#define QWORDS (SC_ROWS * SC_PAD)            // 2176
#define KCH_WORDS (128 * SC_PAD)             // 8704
#define SC_RED_OFF (QWORDS + 2 * KCH_WORDS)  // 19584 words
#define SC_SMEM ((SC_RED_OFF + 256) * 4)     // 79360 B

__global__ __launch_bounds__(256, 1) void scores_softmax_kernel(
    const float* __restrict__ qk, float* __restrict__ attn)
{
    extern __shared__ float smem[];
    uint32_t sb = smem_u32(smem);
    int tid = threadIdx.x;
    int wid = tid >> 5;
    int lane = tid & 31;
    int g4 = lane >> 2;
    int t4 = lane & 3;
    int m_warp = wid & 1;
    int n_warp = wid >> 1;
    int mbase = m_warp * 16;

    int ib = blockIdx.x * SC_ROWS;
    int bh = blockIdx.y;
    int b = bh >> 5;
    int h = bh & 31;

    const float* qbase = qk + (size_t)(b * SEQ) * (2 * D) + h * HDIM;          // q
    const float* kbase = qk + (size_t)(b * SEQ) * (2 * D) + D + h * HDIM;      // k

    // ---- load Q tile (32 x 64) into smem
    #pragma unroll
    for (int i = 0; i < 2; i++) {
        int idx = tid + i * 256;     // 0..511
        int r = idx >> 4;
        int c4 = (idx & 15) * 4;
        float4 v = *(const float4*)(qbase + (size_t)(ib + r) * (2 * D) + c4);
        *(float4*)&smem[r * SC_PAD + c4] = v;
    }

    // ---- K chunk async loader (128 keys x 64 dims)
    auto load_k = [&](int c) {
        uint32_t kb = sb + (QWORDS + (c & 1) * KCH_WORDS) * 4;
        #pragma unroll
        for (int i = 0; i < 8; i++) {
            int idx = tid + i * 256;    // 0..2047
            int r = idx >> 4;
            int c4 = (idx & 15) * 4;
            const float* gp = kbase + (size_t)(c * 128 + r) * (2 * D) + c4;
            CP_ASYNC16(kb + (uint32_t)(r * SC_PAD + c4) * 4, gp);
        }
    };

    load_k(0); CP_COMMIT();
    __syncthreads();   // Q tile visible

    // ---- preload Q fragments (8 k-steps)
    uint32_t aq_off = ((uint32_t)(mbase + (lane & 15)) * SC_PAD + (lane >> 4) * 4) * 4;
    uint32_t qf[8][4];
    #pragma unroll
    for (int s = 0; s < 8; s++)
        ldsm_x4(qf[s][0], qf[s][1], qf[s][2], qf[s][3], sb + aq_off + (uint32_t)(s * 8) * 4);

    uint32_t bk_off = ((uint32_t)(n_warp * 32 + ((lane >> 4) * 8) + (lane & 7)) * SC_PAD
                     + ((lane >> 3) & 1) * 4) * 4;

    float acc[8][4][4];
    #pragma unroll
    for (int c = 0; c < 8; c++)
        #pragma unroll
        for (int ni = 0; ni < 4; ni++)
            #pragma unroll
            for (int r = 0; r < 4; r++) acc[c][ni][r] = 0.0f;

    #pragma unroll
    for (int c = 0; c < 8; c++) {
        if (c + 1 < 8) { load_k(c + 1); CP_COMMIT(); }
        if (c + 1 < 8) { CP_WAIT(1); } else { CP_WAIT(0); }
        __syncthreads();

        uint32_t kb = sb + (QWORDS + (c & 1) * KCH_WORDS) * 4;
        #pragma unroll
        for (int s = 0; s < 8; s++) {
            uint32_t bk[2][4];
            #pragma unroll
            for (int np = 0; np < 2; np++)
                ldsm_x4(bk[np][0], bk[np][1], bk[np][2], bk[np][3],
                        kb + bk_off + (uint32_t)(np * 16 * SC_PAD + s * 8) * 4);
            #pragma unroll
            for (int ni = 0; ni < 4; ni++)
                mma_tf32(acc[c][ni], qf[s][0], qf[s][1], qf[s][2], qf[s][3],
                         bk[ni >> 1][(ni & 1) * 2], bk[ni >> 1][(ni & 1) * 2 + 1]);
        }
        __syncthreads();  // before next load overwrites buffer (c+1)&1's partner
    }

    // ---- softmax over the full row (1024 values spread across 4 n_warps)
    const float scl = rsqrtf((float)D);
    int row0 = mbase + g4;        // local 0..31
    int row1 = row0 + 8;
    float* redm = smem + SC_RED_OFF;        // [32][4]
    float* reds = smem + SC_RED_OFF + 128;  // [32][4]

    float mx0 = -1e30f, mx1 = -1e30f;
    #pragma unroll
    for (int c = 0; c < 8; c++)
        #pragma unroll
        for (int ni = 0; ni < 4; ni++) {
            mx0 = fmaxf(mx0, fmaxf(acc[c][ni][0], acc[c][ni][1]));
            mx1 = fmaxf(mx1, fmaxf(acc[c][ni][2], acc[c][ni][3]));
        }
    mx0 = fmaxf(mx0, __shfl_xor_sync(0xffffffffu, mx0, 1));
    mx0 = fmaxf(mx0, __shfl_xor_sync(0xffffffffu, mx0, 2));
    mx1 = fmaxf(mx1, __shfl_xor_sync(0xffffffffu, mx1, 1));
    mx1 = fmaxf(mx1, __shfl_xor_sync(0xffffffffu, mx1, 2));
    if (t4 == 0) {
        redm[row0 * 4 + n_warp] = mx0;
        redm[row1 * 4 + n_warp] = mx1;
    }
    __syncthreads();
    mx0 = fmaxf(fmaxf(redm[row0 * 4], redm[row0 * 4 + 1]),
                fmaxf(redm[row0 * 4 + 2], redm[row0 * 4 + 3]));
    mx1 = fmaxf(fmaxf(redm[row1 * 4], redm[row1 * 4 + 1]),
                fmaxf(redm[row1 * 4 + 2], redm[row1 * 4 + 3]));

    float s0 = 0.0f, s1 = 0.0f;
    #pragma unroll
    for (int c = 0; c < 8; c++)
        #pragma unroll
        for (int ni = 0; ni < 4; ni++) {
            float e0 = __expf((acc[c][ni][0] - mx0) * scl);
            float e1 = __expf((acc[c][ni][1] - mx0) * scl);
            float e2 = __expf((acc[c][ni][2] - mx1) * scl);
            float e3 = __expf((acc[c][ni][3] - mx1) * scl);
            acc[c][ni][0] = e0; acc[c][ni][1] = e1;
            acc[c][ni][2] = e2; acc[c][ni][3] = e3;
            s0 += e0 + e1;
            s1 += e2 + e3;
        }
    s0 += __shfl_xor_sync(0xffffffffu, s0, 1);
    s0 += __shfl_xor_sync(0xffffffffu, s0, 2);
    s1 += __shfl_xor_sync(0xffffffffu, s1, 1);
    s1 += __shfl_xor_sync(0xffffffffu, s1, 2);
    if (t4 == 0) {
        reds[row0 * 4 + n_warp] = s0;
        reds[row1 * 4 + n_warp] = s1;
    }
    __syncthreads();
    float inv0 = 1.0f / (reds[row0 * 4] + reds[row0 * 4 + 1]
                       + reds[row0 * 4 + 2] + reds[row0 * 4 + 3]);
    float inv1 = 1.0f / (reds[row1 * 4] + reds[row1 * 4 + 1]
                       + reds[row1 * 4 + 2] + reds[row1 * 4 + 3]);

    // ---- write probs
    float* o0 = attn + (size_t)bh * SEQ * SEQ + (size_t)(ib + row0) * SEQ;
    float* o1 = attn + (size_t)bh * SEQ * SEQ + (size_t)(ib + row1) * SEQ;
    #pragma unroll
    for (int c = 0; c < 8; c++)
        #pragma unroll
        for (int ni = 0; ni < 4; ni++) {
            int col = c * 128 + n_warp * 32 + ni * 8 + t4 * 2;
            float2 p0; p0.x = acc[c][ni][0] * inv0; p0.y = acc[c][ni][1] * inv0;
            float2 p1; p1.x = acc[c][ni][2] * inv1; p1.y = acc[c][ni][3] * inv1;
            *(float2*)(o0 + col) = p0;
            *(float2*)(o1 + col) = p1;
        }
}

// ===========================================================================
// Launch
// ===========================================================================
extern "C" void kernel_launch(void* const* d_in, const int* in_sizes, int n_in,
                              void* d_out, int out_size)
{
    const float* x     = (const float*)d_in[0];
    const float* Wq    = (const float*)d_in[1];
    const float* Wk    = (const float*)d_in[2];
    /* d_in[3] = Wv: DEAD in the reference (attended values are discarded). */
    const float* ln1_s = (const float*)d_in[4];
    const float* ln1_b = (const float*)d_in[5];
    const float* ln2_s = (const float*)d_in[6];
    const float* ln2_b = (const float*)d_in[7];
    const float* ff1_w = (const float*)d_in[8];
    const float* ff1_b = (const float*)d_in[9];
    const float* ff2_w = (const float*)d_in[10];
    const float* ff2_b = (const float*)d_in[11];

    float* out  = (float*)d_out;                       // [4,1024,2048]
    float* attn = out + (size_t)NROWS * D;             // [4,32,1024,1024]

    float *h, *x2, *qk, *h2, *t, *wqkt, *f1t, *f2t;
    cudaGetSymbolAddress((void**)&h,    g_h);
    cudaGetSymbolAddress((void**)&x2,   g_x2);
    cudaGetSymbolAddress((void**)&qk,   g_qk);
    cudaGetSymbolAddress((void**)&h2,   g_h2);
    cudaGetSymbolAddress((void**)&t,    g_t);
    cudaGetSymbolAddress((void**)&wqkt, g_wqkt);
    cudaGetSymbolAddress((void**)&f1t,  g_f1t);
    cudaGetSymbolAddress((void**)&f2t,  g_f2t);

    cudaFuncSetAttribute(gemm_tf32_kernel,
                         cudaFuncAttributeMaxDynamicSharedMemorySize, GEMM_SMEM);
    cudaFuncSetAttribute(scores_softmax_kernel,
                         cudaFuncAttributeMaxDynamicSharedMemorySize, SC_SMEM);

    dim3 tg(D / 32, D / 32);                      // (64, 64)

    // Transpose + tf32-round weights. [Wq^T ; Wk^T] stacked for combined GEMM.
    transpose_round_kernel<<<tg, 256>>>(Wq,    wqkt);
    transpose_round_kernel<<<tg, 256>>>(Wk,    wqkt + (size_t)D * D);
    transpose_round_kernel<<<tg, 256>>>(ff1_w, f1t);
    transpose_round_kernel<<<tg, 256>>>(ff2_w, f2t);

    // LN1
    ln_kernel<<<NROWS, 256>>>(x, ln1_s, ln1_b, h, x2);

    // [q|k] = h @ [Wq|Wk]  (one N=4096 GEMM)
    dim3 gqk(2 * D / BN, NROWS / BM);             // (32, 32)
    gemm_tf32_kernel<<<gqk, 256, GEMM_SMEM>>>(h, wqkt, qk, nullptr, nullptr, 2 * D, 0);

    // fused scores + softmax -> attn
    dim3 gsc(SEQ / SC_ROWS, NBATCH * NHEADS);     // (32, 128)
    scores_softmax_kernel<<<gsc, 256, SC_SMEM>>>(qk, attn);

    // LN2
    ln_kernel<<<NROWS, 256>>>(x2, ln2_s, ln2_b, h2, nullptr);

    // FF
    dim3 gff(D / BN, NROWS / BM);                 // (16, 32)
    gemm_tf32_kernel<<<gff, 256, GEMM_SMEM>>>(h2, f1t, t, ff1_b, nullptr, D, 1);
    gemm_tf32_kernel<<<gff, 256, GEMM_SMEM>>>(t, f2t, out, ff2_b, x2, D, 2);
}